// round 2
// baseline (speedup 1.0000x reference)
#include <cuda_runtime.h>
#include <cstdint>

// Problem constants: x (512,1,64,64) f32, weights (4,4,3) f32
// out (512, 12, 31, 31) f32; channel 3k+a, a in {x,y,z}
#define B_   512
#define H_   64
#define W_   64
#define HO_  31
#define WO_  31
#define NK_  4
#define TOTAL_ (B_ * HO_ * WO_)

// [kernel][axis][{alpha,beta}]
__device__ float g_coef[NK_][3][2];

// Per the reduced-density-matrix algebra, only weights[k][0][:] = (theta, phi, omega)
// affect the output. e_a = alpha_a*(s0-s1) + beta_a*cc.
__global__ void coef_kernel(const float* __restrict__ w) {
    int k = threadIdx.x;
    if (k >= NK_) return;
    float th = w[k * 12 + 0];
    float ph = w[k * 12 + 1];
    float om = w[k * 12 + 2];
    float ct = cosf(th), st = sinf(th);
    float chh = cosf(0.5f * th);
    float c2 = chh * chh;          // cos^2(th/2)
    float s2 = 1.0f - c2;          // sin^2(th/2)
    float cpo = cosf(ph + om), spo = sinf(ph + om);
    float cmo = cosf(om - ph), smo = sinf(om - ph);
    g_coef[k][0][0] = st * cosf(ph);
    g_coef[k][0][1] = 2.0f * (c2 * cpo - s2 * cmo);
    g_coef[k][1][0] = st * sinf(ph);
    g_coef[k][1][1] = 2.0f * (c2 * spo + s2 * smo);
    g_coef[k][2][0] = ct;
    g_coef[k][2][1] = -2.0f * st * cosf(om);
}

__global__ __launch_bounds__(256) void qconv_kernel(const float* __restrict__ x,
                                                    float* __restrict__ out) {
    __shared__ float sc[24];
    if (threadIdx.x < 24) sc[threadIdx.x] = ((const float*)g_coef)[threadIdx.x];
    __syncthreads();

    int tid = blockIdx.x * blockDim.x + threadIdx.x;
    if (tid >= TOTAL_) return;

    int ow = tid % WO_;
    int t  = tid / WO_;
    int oh = t % HO_;
    int b  = t / HO_;

    const float* p = x + ((size_t)b * H_ + oh * 2) * W_ + ow * 2;

    float v[4][4];
#pragma unroll
    for (int r = 0; r < 4; r++) {
        float2 a0 = *reinterpret_cast<const float2*>(p + r * W_);
        float2 a1 = *reinterpret_cast<const float2*>(p + r * W_ + 2);
        v[r][0] = a0.x; v[r][1] = a0.y; v[r][2] = a1.x; v[r][3] = a1.y;
    }

    // CNOT-ring folded into index algebra:
    //   amplitude index i = kh*4+kw; MSB(f(i)) = (kh&1)^(kw&1)^((kw>>1)&1)
    //   off-diagonal partner: i ^ 12  (row kh <-> kh^3, same kw)
    float nrm = 0.0f, d = 0.0f, cc = 0.0f;
#pragma unroll
    for (int r = 0; r < 4; r++) {
#pragma unroll
        for (int c = 0; c < 4; c++) {
            float val = v[r][c];
            float sq = val * val;
            nrm += sq;
            int sgn = (r & 1) ^ (c & 1) ^ ((c >> 1) & 1);
            d += sgn ? -sq : sq;
        }
    }
#pragma unroll
    for (int r = 0; r < 2; r++) {
#pragma unroll
        for (int c = 0; c < 4; c++) {
            cc += v[r][c] * v[r ^ 3][c];
        }
    }

    float inv = 1.0f / fmaxf(nrm, 1e-30f);   // exact v/||v|| (eps path in ref cancels)
    d  *= inv;
    cc *= inv;

    // out[b, 3k+a, oh, ow]; consecutive tids -> contiguous addresses per channel
    float* o = out + (size_t)b * (12 * HO_ * WO_) + (size_t)oh * WO_ + ow;
#pragma unroll
    for (int j = 0; j < 12; j++) {
        o[(size_t)j * (HO_ * WO_)] = fmaf(sc[2 * j], d, sc[2 * j + 1] * cc);
    }
}

extern "C" void kernel_launch(void* const* d_in, const int* in_sizes, int n_in,
                              void* d_out, int out_size) {
    const float* x = (const float*)d_in[0];
    const float* w = (const float*)d_in[1];
    if (n_in >= 2 && in_sizes[0] == NK_ * 4 * 3) {  // defensive: swap if metadata order differs
        x = (const float*)d_in[1];
        w = (const float*)d_in[0];
    }
    coef_kernel<<<1, 32>>>(w);
    qconv_kernel<<<(TOTAL_ + 255) / 256, 256>>>(x, (float*)d_out);
}